// round 14
// baseline (speedup 1.0000x reference)
#include <cuda_runtime.h>
#include <cuda_bf16.h>
#include <cuda_fp16.h>
#include <math.h>
#include <stdint.h>

#define S_LEN 2048
#define DIM   1024
#define NH    16
#define DHEAD 64
#define BATCH 2
#define M_ROWS (BATCH * S_LEN)   // 4096
#define NW     (M_ROWS * DIM / 2)
#define WW     (DIM * DIM / 2)

// GEMM planes: bf16x2-packed hi/lo (low half = even k)
__device__ uint32_t g_xh[NW],  g_xl[NW];
__device__ uint32_t g_Wqh[WW], g_Wql[WW];
__device__ uint32_t g_Wkh[WW], g_Wkl[WW];
__device__ uint32_t g_Wvh[WW], g_Wvl[WW];
__device__ uint32_t g_Woh[WW], g_Wol[WW];
// Flash planes: fp16x2-packed. Q pre-scaled by 0.125*log2(e).
__device__ uint32_t g_Qh[NW], g_Ql[NW];
__device__ uint32_t g_Kh[NW], g_Kl[NW];
__device__ uint32_t g_Vth[NW];            // V transposed [n][dh][s/2], single fp16
// AO planes: bf16 (feeds bf16 O-GEMM)
__device__ uint32_t g_AOh[NW], g_AOl[NW];

// ---------------------------------------------------------------------------
// Helpers
// ---------------------------------------------------------------------------
__device__ __forceinline__ uint32_t cvta_smem(const void* p) {
    return (uint32_t)__cvta_generic_to_shared(p);
}
__device__ __forceinline__ void cp_async16(uint32_t dst, const void* src) {
    asm volatile("cp.async.cg.shared.global [%0], [%1], 16;" :: "r"(dst), "l"(src));
}
__device__ __forceinline__ void cp_commit() {
    asm volatile("cp.async.commit_group;");
}
__device__ __forceinline__ uint32_t packbf(float e0, float e1) {
    uint32_t r;
    asm("cvt.rn.bf16x2.f32 %0, %1, %2;" : "=r"(r) : "f"(e1), "f"(e0));
    return r;
}
__device__ __forceinline__ void split2(float e0, float e1, uint32_t& h, uint32_t& l) {
    h = packbf(e0, e1);
    float h0 = __uint_as_float(h << 16);
    float h1 = __uint_as_float(h & 0xFFFF0000u);
    l = packbf(e0 - h0, e1 - h1);
}
__device__ __forceinline__ uint32_t packh2(float e0, float e1) {
    __half2 v = __floats2half2_rn(e0, e1);
    return *reinterpret_cast<uint32_t*>(&v);
}
__device__ __forceinline__ void split2h(float e0, float e1, uint32_t& h, uint32_t& l) {
    __half2 hv = __floats2half2_rn(e0, e1);
    h = *reinterpret_cast<uint32_t*>(&hv);
    float f0 = __half2float(__low2half(hv));
    float f1 = __half2float(__high2half(hv));
    __half2 lv = __floats2half2_rn(e0 - f0, e1 - f1);
    l = *reinterpret_cast<uint32_t*>(&lv);
}
__device__ __forceinline__ float ex2f(float x) {
    float r;
    asm("ex2.approx.f32 %0, %1;" : "=f"(r) : "f"(x));
    return r;
}

#define MMA_BF16(c, a, b)                                                     \
    asm("mma.sync.aligned.m16n8k16.row.col.f32.bf16.bf16.f32 "                \
        "{%0,%1,%2,%3}, {%4,%5,%6,%7}, {%8,%9}, {%0,%1,%2,%3};"               \
        : "+f"((c)[0]), "+f"((c)[1]), "+f"((c)[2]), "+f"((c)[3])              \
        : "r"((a)[0]), "r"((a)[1]), "r"((a)[2]), "r"((a)[3]),                 \
          "r"((b)[0]), "r"((b)[1]))

#define MMA_F16(c, a, b)                                                      \
    asm("mma.sync.aligned.m16n8k16.row.col.f32.f16.f16.f32 "                  \
        "{%0,%1,%2,%3}, {%4,%5,%6,%7}, {%8,%9}, {%0,%1,%2,%3};"               \
        : "+f"((c)[0]), "+f"((c)[1]), "+f"((c)[2]), "+f"((c)[3])              \
        : "r"((a)[0]), "r"((a)[1]), "r"((a)[2]), "r"((a)[3]),                 \
          "r"((b)[0]), "r"((b)[1]))

#define LDSM_X4(r0, r1, r2, r3, addr)                                         \
    asm volatile("ldmatrix.sync.aligned.m8n8.x4.shared.b16 {%0,%1,%2,%3}, [%4];" \
        : "=r"(r0), "=r"(r1), "=r"(r2), "=r"(r3) : "r"(addr))

// ---------------------------------------------------------------------------
// Prepass splits
// ---------------------------------------------------------------------------
__global__ void __launch_bounds__(256) split_bf16(
    const float* __restrict__ in, uint32_t* __restrict__ oh,
    uint32_t* __restrict__ ol, int n4)
{
    const int i = blockIdx.x * blockDim.x + threadIdx.x;
    if (i >= n4) return;
    float4 v = ((const float4*)in)[i];
    uint32_t h0, l0, h1, l1;
    split2(v.x, v.y, h0, l0);
    split2(v.z, v.w, h1, l1);
    ((uint2*)oh)[i] = make_uint2(h0, h1);
    ((uint2*)ol)[i] = make_uint2(l0, l1);
}

struct W4Args {
    const float4* in[4];
    uint2* oh[4];
    uint2* ol[4];
};

__global__ void __launch_bounds__(256) split_w4(W4Args a, int n4)
{
    const int z = blockIdx.y;
    const int i = blockIdx.x * blockDim.x + threadIdx.x;
    if (i >= n4) return;
    float4 v = a.in[z][i];
    uint32_t h0, l0, h1, l1;
    split2(v.x, v.y, h0, l0);
    split2(v.z, v.w, h1, l1);
    a.oh[z][i] = make_uint2(h0, h1);
    a.ol[z][i] = make_uint2(l0, l1);
}

// ---------------------------------------------------------------------------
// 3xBF16 GEMM, 64x64 warp tiles (mi=4, ni=8), 128 threads / 4 warps,
// 2 CTAs/SM. ldmatrix fragments, one barrier per K-chunk.
// MODE 0: fp32 out; 1: Q fp16 planes (x 0.125*log2e); 2: K fp16 planes;
// MODE 3: V transposed SINGLE fp16 plane.
// ---------------------------------------------------------------------------
#define BKW 16
#define AWP 20
#define GTILEW (128 * AWP)
#define QSCALE (0.125f * 1.4426950408889634f)

template <int MODE>
__global__ void __launch_bounds__(128, 2)
gemm_bf16(const uint32_t* __restrict__ Ahg, const uint32_t* __restrict__ Alg,
          const uint32_t* __restrict__ Bhg, const uint32_t* __restrict__ Blg,
          const float* __restrict__ bias,
          float* __restrict__ outf,
          uint32_t* __restrict__ outh, uint32_t* __restrict__ outl)
{
    extern __shared__ uint32_t gsm[];
    uint32_t* Ahs = gsm;
    uint32_t* Als = Ahs + 2 * GTILEW;
    uint32_t* Bhs = Als + 2 * GTILEW;
    uint32_t* Bls = Bhs + 2 * GTILEW;

    const int tid  = threadIdx.x;
    const int lane = tid & 31;
    const int wid  = tid >> 5;           // 0..3
    const int bm = blockIdx.y * 128;
    const int bn = blockIdx.x * 128;
    const int wm = (wid >> 1) * 64;      // 0 or 64
    const int wn = (wid & 1) * 64;       // 0 or 64
    const int gid = lane >> 2;
    const int tig = lane & 3;

    const int a_r  = lane & 15;
    const int a_kw = ((lane >> 4) & 1) * 4;
    const int b_r  = (lane & 7) + ((lane >> 4) & 1) * 8;
    const int b_kw = ((lane >> 3) & 1) * 4;

    // staging: 128 threads; thread pair covers one row (srow, srow+64)
    const int srow = tid >> 1;           // 0..63
    const int sw   = (tid & 1) * 8;      // word offset 0 or 8
    const uint32_t* Ah0 = Ahg + (size_t)(bm + srow) * 512 + sw;
    const uint32_t* Al0 = Alg + (size_t)(bm + srow) * 512 + sw;
    const uint32_t* Bh0 = Bhg + (size_t)(bn + srow) * 512 + sw;
    const uint32_t* Bl0 = Blg + (size_t)(bn + srow) * 512 + sw;

    float acc[32][4];   // [mi*8+ni]
#pragma unroll
    for (int i = 0; i < 32; i++)
#pragma unroll
        for (int j = 0; j < 4; j++) acc[i][j] = 0.0f;

    auto stage = [&](int buf, int ktw) {
        const int o  = buf * GTILEW + srow * AWP + sw;
        const int o2 = o + 64 * AWP;
        cp_async16(cvta_smem(Ahs + o),       Ah0 + ktw);
        cp_async16(cvta_smem(Ahs + o) + 16,  Ah0 + ktw + 4);
        cp_async16(cvta_smem(Ahs + o2),      Ah0 + 64 * 512 + ktw);
        cp_async16(cvta_smem(Ahs + o2) + 16, Ah0 + 64 * 512 + ktw + 4);
        cp_async16(cvta_smem(Als + o),       Al0 + ktw);
        cp_async16(cvta_smem(Als + o) + 16,  Al0 + ktw + 4);
        cp_async16(cvta_smem(Als + o2),      Al0 + 64 * 512 + ktw);
        cp_async16(cvta_smem(Als + o2) + 16, Al0 + 64 * 512 + ktw + 4);
        cp_async16(cvta_smem(Bhs + o),       Bh0 + ktw);
        cp_async16(cvta_smem(Bhs + o) + 16,  Bh0 + ktw + 4);
        cp_async16(cvta_smem(Bhs + o2),      Bh0 + 64 * 512 + ktw);
        cp_async16(cvta_smem(Bhs + o2) + 16, Bh0 + 64 * 512 + ktw + 4);
        cp_async16(cvta_smem(Bls + o),       Bl0 + ktw);
        cp_async16(cvta_smem(Bls + o) + 16,  Bl0 + ktw + 4);
        cp_async16(cvta_smem(Bls + o2),      Bl0 + 64 * 512 + ktw);
        cp_async16(cvta_smem(Bls + o2) + 16, Bl0 + 64 * 512 + ktw + 4);
        cp_commit();
    };

    stage(0, 0);

    int buf = 0;
    for (int ktw = 0; ktw < 512; ktw += BKW, buf ^= 1) {
        asm volatile("cp.async.wait_group 0;");
        __syncthreads();
        if (ktw + BKW < 512) stage(buf ^ 1, ktw + BKW);

        const uint32_t ah_b = cvta_smem(Ahs + buf * GTILEW);
        const uint32_t al_b = cvta_smem(Als + buf * GTILEW);
        const uint32_t bh_b = cvta_smem(Bhs + buf * GTILEW);
        const uint32_t bl_b = cvta_smem(Bls + buf * GTILEW);

#pragma unroll
        for (int ks = 0; ks < 2; ks++) {
            uint32_t ah[4][4], al[4][4];
#pragma unroll
            for (int mi = 0; mi < 4; mi++) {
                const uint32_t ao =
                    ((wm + mi * 16 + a_r) * AWP + ks * 8 + a_kw) * 4;
                LDSM_X4(ah[mi][0], ah[mi][1], ah[mi][2], ah[mi][3], ah_b + ao);
                LDSM_X4(al[mi][0], al[mi][1], al[mi][2], al[mi][3], al_b + ao);
            }
            uint32_t bh[8][2], bl[8][2];
#pragma unroll
            for (int qd = 0; qd < 4; qd++) {
                const uint32_t bo =
                    ((wn + qd * 16 + b_r) * AWP + ks * 8 + b_kw) * 4;
                LDSM_X4(bh[2 * qd][0], bh[2 * qd][1],
                        bh[2 * qd + 1][0], bh[2 * qd + 1][1], bh_b + bo);
                LDSM_X4(bl[2 * qd][0], bl[2 * qd][1],
                        bl[2 * qd + 1][0], bl[2 * qd + 1][1], bl_b + bo);
            }
#pragma unroll
            for (int mi = 0; mi < 4; mi++)
#pragma unroll
                for (int ni = 0; ni < 8; ni++)
                    MMA_BF16(acc[mi * 8 + ni], ah[mi], bh[ni]);
#pragma unroll
            for (int mi = 0; mi < 4; mi++)
#pragma unroll
                for (int ni = 0; ni < 8; ni++)
                    MMA_BF16(acc[mi * 8 + ni], ah[mi], bl[ni]);
#pragma unroll
            for (int mi = 0; mi < 4; mi++)
#pragma unroll
                for (int ni = 0; ni < 8; ni++)
                    MMA_BF16(acc[mi * 8 + ni], al[mi], bh[ni]);
        }
    }

#pragma unroll
    for (int mi = 0; mi < 4; mi++) {
#pragma unroll
        for (int ni = 0; ni < 8; ni++) {
            const int row = bm + wm + mi * 16 + gid;
            const int col = bn + wn + ni * 8 + tig * 2;
            const float b0 = bias[col];
            const float b1 = bias[col + 1];
            const float* c = acc[mi * 8 + ni];
#pragma unroll
            for (int half = 0; half < 2; half++) {
                const int m = row + half * 8;
                float v0 = c[half * 2 + 0] + b0;
                float v1 = c[half * 2 + 1] + b1;
                if (MODE == 0) {
                    float* dst = outf + (size_t)m * DIM + col;
                    dst[0] = v0;
                    dst[1] = v1;
                } else if (MODE == 1 || MODE == 2) {
                    if (MODE == 1) { v0 *= QSCALE; v1 *= QSCALE; }
                    const int b  = m / S_LEN;
                    const int s  = m % S_LEN;
                    const int h  = col / DHEAD;
                    const int dw = (col % DHEAD) >> 1;
                    const size_t idx = ((size_t)(b * NH + h) * S_LEN + s) * 32 + dw;
                    uint32_t hw, lw;
                    split2h(v0, v1, hw, lw);
                    outh[idx] = hw;
                    outl[idx] = lw;
                } else {  // MODE 3: V transposed, single fp16 plane [n][dh][s]
                    const int b  = m / S_LEN;
                    const int s  = m % S_LEN;
                    const int h  = col / DHEAD;
                    const int dh = col % DHEAD;
                    const int n  = b * NH + h;
                    __half* VH = (__half*)outh;
                    const size_t base = ((size_t)n * DHEAD + dh) * S_LEN + s;
                    VH[base]         = __float2half_rn(v0);
                    VH[base + S_LEN] = __float2half_rn(v1);
                }
            }
        }
    }
}

// ---------------------------------------------------------------------------
// Flash attention (unchanged from round 13): QK = 3x fp16; PV = 1x fp16.
// ldmatrix fragments, one barrier per kt. q-tile 128, base-2 softmax.
// ---------------------------------------------------------------------------
#define KWP 36
#define KVW (64 * KWP)
#define KVBUF (3 * KVW)
#define FSMW (2 * KVBUF)

__global__ void __launch_bounds__(256, 2) flash_f16()
{
    extern __shared__ uint32_t fsw[];

    const int qt   = (int)gridDim.x - 1 - (int)blockIdx.x;
    const int n    = blockIdx.y;
    const int tid  = threadIdx.x;
    const int lane = tid & 31;
    const int w    = tid >> 5;
    const int gid  = lane >> 2;
    const int tig  = lane & 3;

    const int r0 = w * 16 + gid;
    const int r1 = r0 + 8;

    const int b_r  = (lane & 7) + ((lane >> 4) & 1) * 8;
    const int b_kw = ((lane >> 3) & 1) * 4;

    const uint32_t* Qhg = g_Qh + ((size_t)n * S_LEN + qt * 128) * 32;
    const uint32_t* Qlg = g_Ql + ((size_t)n * S_LEN + qt * 128) * 32;
    uint32_t qh[4][4], ql[4][4];
#pragma unroll
    for (int ks = 0; ks < 4; ks++) {
        const int w0 = ks * 8 + tig;
        qh[ks][0] = Qhg[r0 * 32 + w0];
        qh[ks][1] = Qhg[r1 * 32 + w0];
        qh[ks][2] = Qhg[r0 * 32 + w0 + 4];
        qh[ks][3] = Qhg[r1 * 32 + w0 + 4];
        ql[ks][0] = Qlg[r0 * 32 + w0];
        ql[ks][1] = Qlg[r1 * 32 + w0];
        ql[ks][2] = Qlg[r0 * 32 + w0 + 4];
        ql[ks][3] = Qlg[r1 * 32 + w0 + 4];
    }

    float m0 = -1.0e30f, m1 = -1.0e30f, l0 = 0.0f, l1 = 0.0f;
    float o[8][4];
#pragma unroll
    for (int i = 0; i < 8; i++)
#pragma unroll
        for (int j = 0; j < 4; j++) o[i][j] = 0.0f;

    const int srow = tid >> 2;
    const int soff = (tid & 3) * 8;

    const uint32_t* Khg = g_Kh  + (size_t)n * S_LEN * 32;
    const uint32_t* Klg = g_Kl  + (size_t)n * S_LEN * 32;
    const uint32_t* Vhg = g_Vth + (size_t)n * DHEAD * (S_LEN / 2);

    auto stage = [&](int buf, int kt) {
        const uint32_t* sKh = Khg + (size_t)(kt * 64 + srow) * 32 + soff;
        const uint32_t* sKl = Klg + (size_t)(kt * 64 + srow) * 32 + soff;
        const uint32_t* sVh = Vhg + (size_t)srow * (S_LEN / 2) + kt * 32 + soff;
        const uint32_t base = cvta_smem(fsw + buf * KVBUF + srow * KWP + soff);
        cp_async16(base,                    sKh);
        cp_async16(base + 16,               sKh + 4);
        cp_async16(base + KVW * 4,          sKl);
        cp_async16(base + KVW * 4 + 16,     sKl + 4);
        cp_async16(base + 2 * KVW * 4,      sVh);
        cp_async16(base + 2 * KVW * 4 + 16, sVh + 4);
        cp_commit();
    };

    const int ktmax = 2 * qt + 1;
    stage(0, 0);

    int buf = 0;
    for (int kt = 0; kt <= ktmax; kt++, buf ^= 1) {
        asm volatile("cp.async.wait_group 0;");
        __syncthreads();
        if (kt < ktmax) stage(buf ^ 1, kt + 1);

        const uint32_t kh_b = cvta_smem(fsw + buf * KVBUF);
        const uint32_t kl_b = kh_b + KVW * 4;
        const uint32_t vh_b = kh_b + 2 * KVW * 4;

        // ---- S = Q K^T (3x fp16, f32 acc; hh/hl/lh sweeps) ----
        float s[8][4];
#pragma unroll
        for (int i = 0; i < 8; i++)
#pragma unroll
            for (int j = 0; j < 4; j++) s[i][j] = 0.0f;

#pragma unroll
        for (int ks = 0; ks < 4; ks++) {
            uint32_t kbh[8][2], kbl[8][2];
#pragma unroll
            for (int qd = 0; qd < 4; qd++) {
                const uint32_t bo = ((qd * 16 + b_r) * KWP + ks * 8 + b_kw) * 4;
                LDSM_X4(kbh[2 * qd][0], kbh[2 * qd][1],
                        kbh[2 * qd + 1][0], kbh[2 * qd + 1][1], kh_b + bo);
                LDSM_X4(kbl[2 * qd][0], kbl[2 * qd][1],
                        kbl[2 * qd + 1][0], kbl[2 * qd + 1][1], kl_b + bo);
            }
#pragma unroll
            for (int ni = 0; ni < 8; ni++)
                MMA_F16(s[ni], qh[ks], kbh[ni]);
#pragma unroll
            for (int ni = 0; ni < 8; ni++)
                MMA_F16(s[ni], qh[ks], kbl[ni]);
#pragma unroll
            for (int ni = 0; ni < 8; ni++)
                MMA_F16(s[ni], ql[ks], kbh[ni]);
        }

        // ---- causal mask (only last two kt tiles can touch the diagonal) ----
        if (kt >= 2 * qt) {
            const int gr0 = qt * 128 + r0;
            const int gr1 = gr0 + 8;
#pragma unroll
            for (int ni = 0; ni < 8; ni++) {
                const int gc = kt * 64 + ni * 8 + tig * 2;
                if (gc > gr0)     s[ni][0] = -1.0e30f;
                if (gc + 1 > gr0) s[ni][1] = -1.0e30f;
                if (gc > gr1)     s[ni][2] = -1.0e30f;
                if (gc + 1 > gr1) s[ni][3] = -1.0e30f;
            }
        }

        // ---- online softmax (base 2) ----
        float mx0 = -1.0e30f, mx1 = -1.0e30f;
#pragma unroll
        for (int ni = 0; ni < 8; ni++) {
            mx0 = fmaxf(mx0, fmaxf(s[ni][0], s[ni][1]));
            mx1 = fmaxf(mx1, fmaxf(s[ni][2], s[ni][3]));
        }
        mx0 = fmaxf(mx0, __shfl_xor_sync(0xffffffffu, mx0, 1));
        mx0 = fmaxf(mx0, __shfl_xor_sync(0xffffffffu, mx0, 2));
        mx1 = fmaxf(mx1, __shfl_xor_sync(0xffffffffu, mx1, 1));
        mx1 = fmaxf(mx1, __shfl_xor_sync(0xffffffffu, mx1, 2));

        const float mn0 = fmaxf(m0, mx0);
        const float mn1 = fmaxf(m1, mx1);
        const float a0 = ex2f(m0 - mn0);
        const float a1 = ex2f(m1 - mn1);
        m0 = mn0; m1 = mn1;

        float sum0 = 0.0f, sum1 = 0.0f;
#pragma unroll
        for (int ni = 0; ni < 8; ni++) {
            s[ni][0] = ex2f(s[ni][0] - mn0);
            s[ni][1] = ex2f(s[ni][1] - mn0);
            s[ni][2] = ex2f(s[ni][2] - mn1);
            s[ni][3] = ex2f(s[ni][3] - mn1);
            sum0 += s[ni][0] + s[ni][1];
            sum1 += s[ni][2] + s[ni][3];
        }
        sum0 += __shfl_xor_sync(0xffffffffu, sum0, 1);
        sum0 += __shfl_xor_sync(0xffffffffu, sum0, 2);
        sum1 += __shfl_xor_sync(0xffffffffu, sum1, 1);
        sum1 += __shfl_xor_sync(0xffffffffu, sum1, 2);
        l0 = l0 * a0 + sum0;
        l1 = l1 * a1 + sum1;

#pragma unroll
        for (int ni = 0; ni < 8; ni++) {
            o[ni][0] *= a0; o[ni][1] *= a0;
            o[ni][2] *= a1; o[ni][3] *= a1;
        }

        // ---- O += P V : single fp16 P, single fp16 V ----
#pragma unroll
        for (int j = 0; j < 4; j++) {
            uint32_t pa[4];
            pa[0] = packh2(s[2 * j][0],     s[2 * j][1]);
            pa[1] = packh2(s[2 * j][2],     s[2 * j][3]);
            pa[2] = packh2(s[2 * j + 1][0], s[2 * j + 1][1]);
            pa[3] = packh2(s[2 * j + 1][2], s[2 * j + 1][3]);
            uint32_t vb[8][2];
#pragma unroll
            for (int qd = 0; qd < 4; qd++) {
                const uint32_t vo = ((qd * 16 + b_r) * KWP + j * 8 + b_kw) * 4;
                LDSM_X4(vb[2 * qd][0], vb[2 * qd][1],
                        vb[2 * qd + 1][0], vb[2 * qd + 1][1], vh_b + vo);
            }
#pragma unroll
            for (int ni = 0; ni < 8; ni++)
                MMA_F16(o[ni], pa, vb[ni]);
        }
    }

    // ---- epilogue: normalize, split (bf16 planes), store concat-head ----
    const float inv0 = 1.0f / l0;
    const float inv1 = 1.0f / l1;
    const int b = n >> 4;
    const int h = n & 15;
    const int rowg0 = b * S_LEN + qt * 128 + r0;
    const int rowg1 = rowg0 + 8;
#pragma unroll
    for (int ni = 0; ni < 8; ni++) {
        const int cw = h * 32 + ni * 4 + tig;
        uint32_t hw, lw;
        split2(o[ni][0] * inv0, o[ni][1] * inv0, hw, lw);
        g_AOh[(size_t)rowg0 * 512 + cw] = hw;
        g_AOl[(size_t)rowg0 * 512 + cw] = lw;
        split2(o[ni][2] * inv1, o[ni][3] * inv1, hw, lw);
        g_AOh[(size_t)rowg1 * 512 + cw] = hw;
        g_AOl[(size_t)rowg1 * 512 + cw] = lw;
    }
}

// ---------------------------------------------------------------------------
// kernel_launch: x, mask, Wq, bq, Wk, bk, Wv, bv, Wo, bo
// ---------------------------------------------------------------------------
extern "C" void kernel_launch(void* const* d_in, const int* in_sizes, int n_in,
                              void* d_out, int out_size)
{
    const float* x  = (const float*)d_in[0];
    const float* Wq = (const float*)d_in[2];
    const float* bq = (const float*)d_in[3];
    const float* Wk = (const float*)d_in[4];
    const float* bk = (const float*)d_in[5];
    const float* Wv = (const float*)d_in[6];
    const float* bv = (const float*)d_in[7];
    const float* Wo = (const float*)d_in[8];
    const float* bo = (const float*)d_in[9];
    float* out = (float*)d_out;

    uint32_t *xh, *xl, *Wqh, *Wql, *Wkh, *Wkl, *Wvh, *Wvl, *Woh, *Wol;
    uint32_t *Qh, *Ql, *Kh, *Kl, *Vth, *AOh, *AOl;
    cudaGetSymbolAddress((void**)&xh,  g_xh);  cudaGetSymbolAddress((void**)&xl,  g_xl);
    cudaGetSymbolAddress((void**)&Wqh, g_Wqh); cudaGetSymbolAddress((void**)&Wql, g_Wql);
    cudaGetSymbolAddress((void**)&Wkh, g_Wkh); cudaGetSymbolAddress((void**)&Wkl, g_Wkl);
    cudaGetSymbolAddress((void**)&Wvh, g_Wvh); cudaGetSymbolAddress((void**)&Wvl, g_Wvl);
    cudaGetSymbolAddress((void**)&Woh, g_Woh); cudaGetSymbolAddress((void**)&Wol, g_Wol);
    cudaGetSymbolAddress((void**)&Qh,  g_Qh);  cudaGetSymbolAddress((void**)&Ql,  g_Ql);
    cudaGetSymbolAddress((void**)&Kh,  g_Kh);  cudaGetSymbolAddress((void**)&Kl,  g_Kl);
    cudaGetSymbolAddress((void**)&Vth, g_Vth);
    cudaGetSymbolAddress((void**)&AOh, g_AOh); cudaGetSymbolAddress((void**)&AOl, g_AOl);

    split_bf16<<<(M_ROWS * DIM / 4 + 255) / 256, 256>>>(x, xh, xl, M_ROWS * DIM / 4);
    {
        W4Args a;
        a.in[0] = (const float4*)Wq; a.oh[0] = (uint2*)Wqh; a.ol[0] = (uint2*)Wql;
        a.in[1] = (const float4*)Wk; a.oh[1] = (uint2*)Wkh; a.ol[1] = (uint2*)Wkl;
        a.in[2] = (const float4*)Wv; a.oh[2] = (uint2*)Wvh; a.ol[2] = (uint2*)Wvl;
        a.in[3] = (const float4*)Wo; a.oh[3] = (uint2*)Woh; a.ol[3] = (uint2*)Wol;
        const int n4 = DIM * DIM / 4;
        split_w4<<<dim3((n4 + 255) / 256, 4), 256>>>(a, n4);
    }

    const int gsmem = 8 * GTILEW * (int)sizeof(uint32_t);  // 81920
    cudaFuncSetAttribute(gemm_bf16<0>, cudaFuncAttributeMaxDynamicSharedMemorySize, gsmem);
    cudaFuncSetAttribute(gemm_bf16<1>, cudaFuncAttributeMaxDynamicSharedMemorySize, gsmem);
    cudaFuncSetAttribute(gemm_bf16<2>, cudaFuncAttributeMaxDynamicSharedMemorySize, gsmem);
    cudaFuncSetAttribute(gemm_bf16<3>, cudaFuncAttributeMaxDynamicSharedMemorySize, gsmem);

    const dim3 ggrid(DIM / 128, M_ROWS / 128);  // (8, 32)
    gemm_bf16<1><<<ggrid, 128, gsmem>>>(xh, xl, Wqh, Wql, bq, nullptr, Qh, Ql);
    gemm_bf16<2><<<ggrid, 128, gsmem>>>(xh, xl, Wkh, Wkl, bk, nullptr, Kh, Kl);
    gemm_bf16<3><<<ggrid, 128, gsmem>>>(xh, xl, Wvh, Wvl, bv, nullptr, Vth, nullptr);

    const int fsmem = FSMW * (int)sizeof(uint32_t);  // 55296
    cudaFuncSetAttribute(flash_f16, cudaFuncAttributeMaxDynamicSharedMemorySize, fsmem);
    flash_f16<<<dim3(S_LEN / 128, BATCH * NH), 256, fsmem>>>();

    gemm_bf16<0><<<ggrid, 128, gsmem>>>(AOh, AOl, Woh, Wol, bo, out, nullptr, nullptr);
}

// round 15
// speedup vs baseline: 1.0876x; 1.0876x over previous
#include <cuda_runtime.h>
#include <cuda_bf16.h>
#include <cuda_fp16.h>
#include <math.h>
#include <stdint.h>

#define S_LEN 2048
#define DIM   1024
#define NH    16
#define DHEAD 64
#define BATCH 2
#define M_ROWS (BATCH * S_LEN)   // 4096
#define NW     (M_ROWS * DIM / 2)
#define WW     (DIM * DIM / 2)

// GEMM planes: bf16x2-packed hi/lo (low half = even k)
__device__ uint32_t g_xh[NW],  g_xl[NW];
__device__ uint32_t g_Wqh[WW], g_Wql[WW];
__device__ uint32_t g_Wkh[WW], g_Wkl[WW];
__device__ uint32_t g_Wvh[WW], g_Wvl[WW];
__device__ uint32_t g_Woh[WW], g_Wol[WW];
// Flash planes: fp16x2-packed. Q pre-scaled by 0.125*log2(e).
__device__ uint32_t g_Qh[NW], g_Ql[NW];
__device__ uint32_t g_Kh[NW], g_Kl[NW];
__device__ uint32_t g_Vth[NW];            // V transposed [n][dh][s/2], single fp16
// AO planes: bf16 (feeds bf16 O-GEMM)
__device__ uint32_t g_AOh[NW], g_AOl[NW];

// ---------------------------------------------------------------------------
// Helpers
// ---------------------------------------------------------------------------
__device__ __forceinline__ uint32_t cvta_smem(const void* p) {
    return (uint32_t)__cvta_generic_to_shared(p);
}
__device__ __forceinline__ void cp_async16(uint32_t dst, const void* src) {
    asm volatile("cp.async.cg.shared.global [%0], [%1], 16;" :: "r"(dst), "l"(src));
}
__device__ __forceinline__ void cp_commit() {
    asm volatile("cp.async.commit_group;");
}
__device__ __forceinline__ uint32_t packbf(float e0, float e1) {
    uint32_t r;
    asm("cvt.rn.bf16x2.f32 %0, %1, %2;" : "=r"(r) : "f"(e1), "f"(e0));
    return r;
}
__device__ __forceinline__ void split2(float e0, float e1, uint32_t& h, uint32_t& l) {
    h = packbf(e0, e1);
    float h0 = __uint_as_float(h << 16);
    float h1 = __uint_as_float(h & 0xFFFF0000u);
    l = packbf(e0 - h0, e1 - h1);
}
__device__ __forceinline__ uint32_t packh2(float e0, float e1) {
    __half2 v = __floats2half2_rn(e0, e1);
    return *reinterpret_cast<uint32_t*>(&v);
}
__device__ __forceinline__ void split2h(float e0, float e1, uint32_t& h, uint32_t& l) {
    __half2 hv = __floats2half2_rn(e0, e1);
    h = *reinterpret_cast<uint32_t*>(&hv);
    float f0 = __half2float(__low2half(hv));
    float f1 = __half2float(__high2half(hv));
    __half2 lv = __floats2half2_rn(e0 - f0, e1 - f1);
    l = *reinterpret_cast<uint32_t*>(&lv);
}
__device__ __forceinline__ float ex2f(float x) {
    float r;
    asm("ex2.approx.f32 %0, %1;" : "=f"(r) : "f"(x));
    return r;
}

#define MMA_BF16(c, a, b)                                                     \
    asm("mma.sync.aligned.m16n8k16.row.col.f32.bf16.bf16.f32 "                \
        "{%0,%1,%2,%3}, {%4,%5,%6,%7}, {%8,%9}, {%0,%1,%2,%3};"               \
        : "+f"((c)[0]), "+f"((c)[1]), "+f"((c)[2]), "+f"((c)[3])              \
        : "r"((a)[0]), "r"((a)[1]), "r"((a)[2]), "r"((a)[3]),                 \
          "r"((b)[0]), "r"((b)[1]))

#define MMA_F16(c, a, b)                                                      \
    asm("mma.sync.aligned.m16n8k16.row.col.f32.f16.f16.f32 "                  \
        "{%0,%1,%2,%3}, {%4,%5,%6,%7}, {%8,%9}, {%0,%1,%2,%3};"               \
        : "+f"((c)[0]), "+f"((c)[1]), "+f"((c)[2]), "+f"((c)[3])              \
        : "r"((a)[0]), "r"((a)[1]), "r"((a)[2]), "r"((a)[3]),                 \
          "r"((b)[0]), "r"((b)[1]))

#define LDSM_X4(r0, r1, r2, r3, addr)                                         \
    asm volatile("ldmatrix.sync.aligned.m8n8.x4.shared.b16 {%0,%1,%2,%3}, [%4];" \
        : "=r"(r0), "=r"(r1), "=r"(r2), "=r"(r3) : "r"(addr))

// ---------------------------------------------------------------------------
// Prepass splits
// ---------------------------------------------------------------------------
__global__ void __launch_bounds__(256) split_bf16(
    const float* __restrict__ in, uint32_t* __restrict__ oh,
    uint32_t* __restrict__ ol, int n4)
{
    const int i = blockIdx.x * blockDim.x + threadIdx.x;
    if (i >= n4) return;
    float4 v = ((const float4*)in)[i];
    uint32_t h0, l0, h1, l1;
    split2(v.x, v.y, h0, l0);
    split2(v.z, v.w, h1, l1);
    ((uint2*)oh)[i] = make_uint2(h0, h1);
    ((uint2*)ol)[i] = make_uint2(l0, l1);
}

struct W4Args {
    const float4* in[4];
    uint2* oh[4];
    uint2* ol[4];
};

__global__ void __launch_bounds__(256) split_w4(W4Args a, int n4)
{
    const int z = blockIdx.y;
    const int i = blockIdx.x * blockDim.x + threadIdx.x;
    if (i >= n4) return;
    float4 v = a.in[z][i];
    uint32_t h0, l0, h1, l1;
    split2(v.x, v.y, h0, l0);
    split2(v.z, v.w, h1, l1);
    a.oh[z][i] = make_uint2(h0, h1);
    a.ol[z][i] = make_uint2(l0, l1);
}

// ---------------------------------------------------------------------------
// GEMM core (R13 shape): 256 threads, 8 warps (4m x 2n), warp tile 32x64,
// ldmatrix fragments, one barrier per K-chunk, 3xBF16.
// Shared mainloop; epilogue by MODE (0: fp32 out, 1: Q, 2: K, 3: V-transposed).
// ---------------------------------------------------------------------------
#define BKW 16
#define AWP 20
#define GTILEW (128 * AWP)
#define QSCALE (0.125f * 1.4426950408889634f)

struct QKVArgs {
    const uint32_t* Bh[3];
    const uint32_t* Bl[3];
    const float*    bias[3];
    uint32_t*       outh[3];
    uint32_t*       outl[3];
};

template <int MODE>
__device__ __forceinline__ void gemm_core(
    const uint32_t* __restrict__ Ahg, const uint32_t* __restrict__ Alg,
    const uint32_t* __restrict__ Bhg, const uint32_t* __restrict__ Blg,
    const float* __restrict__ bias,
    float* __restrict__ outf,
    uint32_t* __restrict__ outh, uint32_t* __restrict__ outl,
    uint32_t* gsm, int bm, int bn)
{
    uint32_t* Ahs = gsm;
    uint32_t* Als = Ahs + 2 * GTILEW;
    uint32_t* Bhs = Als + 2 * GTILEW;
    uint32_t* Bls = Bhs + 2 * GTILEW;

    const int tid  = threadIdx.x;
    const int lane = tid & 31;
    const int wid  = tid >> 5;
    const int wm = (wid >> 1) * 32;
    const int wn = (wid & 1) * 64;
    const int gid = lane >> 2;
    const int tig = lane & 3;

    const int a_r  = lane & 15;
    const int a_kw = ((lane >> 4) & 1) * 4;
    const int b_r  = (lane & 7) + ((lane >> 4) & 1) * 8;
    const int b_kw = ((lane >> 3) & 1) * 4;

    const int lrow = tid >> 2;
    const int lkw  = (tid & 3) * 4;
    const uint32_t* Ah0 = Ahg + (size_t)(bm + lrow) * 512 + lkw;
    const uint32_t* Al0 = Alg + (size_t)(bm + lrow) * 512 + lkw;
    const uint32_t* Bh0 = Bhg + (size_t)(bn + lrow) * 512 + lkw;
    const uint32_t* Bl0 = Blg + (size_t)(bn + lrow) * 512 + lkw;

    float acc[16][4];
#pragma unroll
    for (int i = 0; i < 16; i++)
#pragma unroll
        for (int j = 0; j < 4; j++) acc[i][j] = 0.0f;

    auto stage = [&](int buf, int ktw) {
        const int o  = buf * GTILEW + lrow * AWP + lkw;
        const int o2 = o + 64 * AWP;
        cp_async16(cvta_smem(Ahs + o),  Ah0 + ktw);
        cp_async16(cvta_smem(Ahs + o2), Ah0 + 64 * 512 + ktw);
        cp_async16(cvta_smem(Als + o),  Al0 + ktw);
        cp_async16(cvta_smem(Als + o2), Al0 + 64 * 512 + ktw);
        cp_async16(cvta_smem(Bhs + o),  Bh0 + ktw);
        cp_async16(cvta_smem(Bhs + o2), Bh0 + 64 * 512 + ktw);
        cp_async16(cvta_smem(Bls + o),  Bl0 + ktw);
        cp_async16(cvta_smem(Bls + o2), Bl0 + 64 * 512 + ktw);
        cp_commit();
    };

    stage(0, 0);

    int buf = 0;
    for (int ktw = 0; ktw < 512; ktw += BKW, buf ^= 1) {
        asm volatile("cp.async.wait_group 0;");
        __syncthreads();
        if (ktw + BKW < 512) stage(buf ^ 1, ktw + BKW);

        const uint32_t ah_b = cvta_smem(Ahs + buf * GTILEW);
        const uint32_t al_b = cvta_smem(Als + buf * GTILEW);
        const uint32_t bh_b = cvta_smem(Bhs + buf * GTILEW);
        const uint32_t bl_b = cvta_smem(Bls + buf * GTILEW);

#pragma unroll
        for (int ks = 0; ks < 2; ks++) {
            uint32_t ah[2][4], al[2][4];
#pragma unroll
            for (int mi = 0; mi < 2; mi++) {
                const uint32_t ao =
                    ((wm + mi * 16 + a_r) * AWP + ks * 8 + a_kw) * 4;
                LDSM_X4(ah[mi][0], ah[mi][1], ah[mi][2], ah[mi][3], ah_b + ao);
                LDSM_X4(al[mi][0], al[mi][1], al[mi][2], al[mi][3], al_b + ao);
            }
            uint32_t bh[8][2], bl[8][2];
#pragma unroll
            for (int qd = 0; qd < 4; qd++) {
                const uint32_t bo =
                    ((wn + qd * 16 + b_r) * AWP + ks * 8 + b_kw) * 4;
                LDSM_X4(bh[2 * qd][0], bh[2 * qd][1],
                        bh[2 * qd + 1][0], bh[2 * qd + 1][1], bh_b + bo);
                LDSM_X4(bl[2 * qd][0], bl[2 * qd][1],
                        bl[2 * qd + 1][0], bl[2 * qd + 1][1], bl_b + bo);
            }
#pragma unroll
            for (int mi = 0; mi < 2; mi++)
#pragma unroll
                for (int ni = 0; ni < 8; ni++)
                    MMA_BF16(acc[mi * 8 + ni], ah[mi], bh[ni]);
#pragma unroll
            for (int mi = 0; mi < 2; mi++)
#pragma unroll
                for (int ni = 0; ni < 8; ni++)
                    MMA_BF16(acc[mi * 8 + ni], ah[mi], bl[ni]);
#pragma unroll
            for (int mi = 0; mi < 2; mi++)
#pragma unroll
                for (int ni = 0; ni < 8; ni++)
                    MMA_BF16(acc[mi * 8 + ni], al[mi], bh[ni]);
        }
    }

#pragma unroll
    for (int mi = 0; mi < 2; mi++) {
#pragma unroll
        for (int ni = 0; ni < 8; ni++) {
            const int row = bm + wm + mi * 16 + gid;
            const int col = bn + wn + ni * 8 + tig * 2;
            const float b0 = bias[col - bn + bn];   // plain index
            const float b1 = bias[col + 1 - bn + bn];
            const float* c = acc[mi * 8 + ni];
#pragma unroll
            for (int half = 0; half < 2; half++) {
                const int m = row + half * 8;
                float v0 = c[half * 2 + 0] + b0;
                float v1 = c[half * 2 + 1] + b1;
                if (MODE == 0) {
                    float* dst = outf + (size_t)m * DIM + col;
                    dst[0] = v0;
                    dst[1] = v1;
                } else if (MODE == 1 || MODE == 2) {
                    if (MODE == 1) { v0 *= QSCALE; v1 *= QSCALE; }
                    const int b  = m / S_LEN;
                    const int s  = m % S_LEN;
                    const int h  = col / DHEAD;
                    const int dw = (col % DHEAD) >> 1;
                    const size_t idx = ((size_t)(b * NH + h) * S_LEN + s) * 32 + dw;
                    uint32_t hw, lw;
                    split2h(v0, v1, hw, lw);
                    outh[idx] = hw;
                    outl[idx] = lw;
                } else {  // MODE 3: V transposed, single fp16 plane [n][dh][s]
                    const int b  = m / S_LEN;
                    const int s  = m % S_LEN;
                    const int h  = col / DHEAD;
                    const int dh = col % DHEAD;
                    const int n  = b * NH + h;
                    __half* VH = (__half*)outh;
                    const size_t base = ((size_t)n * DHEAD + dh) * S_LEN + s;
                    VH[base]         = __float2half_rn(v0);
                    VH[base + S_LEN] = __float2half_rn(v1);
                }
            }
        }
    }
}

// Fused QKV: grid (8, 32, 3); z selects weight/bias/output + epilogue mode.
__global__ void __launch_bounds__(256, 2)
gemm_qkv(const uint32_t* __restrict__ Ahg, const uint32_t* __restrict__ Alg,
         QKVArgs args)
{
    extern __shared__ uint32_t gsm[];
    const int z  = blockIdx.z;
    const int bm = blockIdx.y * 128;
    const int bn = blockIdx.x * 128;
    if (z == 0) {
        gemm_core<1>(Ahg, Alg, args.Bh[0], args.Bl[0], args.bias[0],
                     nullptr, args.outh[0], args.outl[0], gsm, bm, bn);
    } else if (z == 1) {
        gemm_core<2>(Ahg, Alg, args.Bh[1], args.Bl[1], args.bias[1],
                     nullptr, args.outh[1], args.outl[1], gsm, bm, bn);
    } else {
        gemm_core<3>(Ahg, Alg, args.Bh[2], args.Bl[2], args.bias[2],
                     nullptr, args.outh[2], nullptr, gsm, bm, bn);
    }
}

// O projection: fp32 out.
__global__ void __launch_bounds__(256, 2)
gemm_o(const uint32_t* __restrict__ Ahg, const uint32_t* __restrict__ Alg,
       const uint32_t* __restrict__ Bhg, const uint32_t* __restrict__ Blg,
       const float* __restrict__ bias, float* __restrict__ outf)
{
    extern __shared__ uint32_t gsm[];
    gemm_core<0>(Ahg, Alg, Bhg, Blg, bias, outf, nullptr, nullptr,
                 gsm, blockIdx.y * 128, blockIdx.x * 128);
}

// ---------------------------------------------------------------------------
// Flash attention (R13): QK = 3x fp16; PV = 1x fp16. ldmatrix fragments,
// one barrier per kt. q-tile 128, base-2 softmax.
// ---------------------------------------------------------------------------
#define KWP 36
#define KVW (64 * KWP)
#define KVBUF (3 * KVW)
#define FSMW (2 * KVBUF)

__global__ void __launch_bounds__(256, 2) flash_f16()
{
    extern __shared__ uint32_t fsw[];

    const int qt   = (int)gridDim.x - 1 - (int)blockIdx.x;
    const int n    = blockIdx.y;
    const int tid  = threadIdx.x;
    const int lane = tid & 31;
    const int w    = tid >> 5;
    const int gid  = lane >> 2;
    const int tig  = lane & 3;

    const int r0 = w * 16 + gid;
    const int r1 = r0 + 8;

    const int b_r  = (lane & 7) + ((lane >> 4) & 1) * 8;
    const int b_kw = ((lane >> 3) & 1) * 4;

    const uint32_t* Qhg = g_Qh + ((size_t)n * S_LEN + qt * 128) * 32;
    const uint32_t* Qlg = g_Ql + ((size_t)n * S_LEN + qt * 128) * 32;
    uint32_t qh[4][4], ql[4][4];
#pragma unroll
    for (int ks = 0; ks < 4; ks++) {
        const int w0 = ks * 8 + tig;
        qh[ks][0] = Qhg[r0 * 32 + w0];
        qh[ks][1] = Qhg[r1 * 32 + w0];
        qh[ks][2] = Qhg[r0 * 32 + w0 + 4];
        qh[ks][3] = Qhg[r1 * 32 + w0 + 4];
        ql[ks][0] = Qlg[r0 * 32 + w0];
        ql[ks][1] = Qlg[r1 * 32 + w0];
        ql[ks][2] = Qlg[r0 * 32 + w0 + 4];
        ql[ks][3] = Qlg[r1 * 32 + w0 + 4];
    }

    float m0 = -1.0e30f, m1 = -1.0e30f, l0 = 0.0f, l1 = 0.0f;
    float o[8][4];
#pragma unroll
    for (int i = 0; i < 8; i++)
#pragma unroll
        for (int j = 0; j < 4; j++) o[i][j] = 0.0f;

    const int srow = tid >> 2;
    const int soff = (tid & 3) * 8;

    const uint32_t* Khg = g_Kh  + (size_t)n * S_LEN * 32;
    const uint32_t* Klg = g_Kl  + (size_t)n * S_LEN * 32;
    const uint32_t* Vhg = g_Vth + (size_t)n * DHEAD * (S_LEN / 2);

    auto stage = [&](int buf, int kt) {
        const uint32_t* sKh = Khg + (size_t)(kt * 64 + srow) * 32 + soff;
        const uint32_t* sKl = Klg + (size_t)(kt * 64 + srow) * 32 + soff;
        const uint32_t* sVh = Vhg + (size_t)srow * (S_LEN / 2) + kt * 32 + soff;
        const uint32_t base = cvta_smem(fsw + buf * KVBUF + srow * KWP + soff);
        cp_async16(base,                    sKh);
        cp_async16(base + 16,               sKh + 4);
        cp_async16(base + KVW * 4,          sKl);
        cp_async16(base + KVW * 4 + 16,     sKl + 4);
        cp_async16(base + 2 * KVW * 4,      sVh);
        cp_async16(base + 2 * KVW * 4 + 16, sVh + 4);
        cp_commit();
    };

    const int ktmax = 2 * qt + 1;
    stage(0, 0);

    int buf = 0;
    for (int kt = 0; kt <= ktmax; kt++, buf ^= 1) {
        asm volatile("cp.async.wait_group 0;");
        __syncthreads();
        if (kt < ktmax) stage(buf ^ 1, kt + 1);

        const uint32_t kh_b = cvta_smem(fsw + buf * KVBUF);
        const uint32_t kl_b = kh_b + KVW * 4;
        const uint32_t vh_b = kh_b + 2 * KVW * 4;

        // ---- S = Q K^T (3x fp16, f32 acc; hh/hl/lh sweeps) ----
        float s[8][4];
#pragma unroll
        for (int i = 0; i < 8; i++)
#pragma unroll
            for (int j = 0; j < 4; j++) s[i][j] = 0.0f;

#pragma unroll
        for (int ks = 0; ks < 4; ks++) {
            uint32_t kbh[8][2], kbl[8][2];
#pragma unroll
            for (int qd = 0; qd < 4; qd++) {
                const uint32_t bo = ((qd * 16 + b_r) * KWP + ks * 8 + b_kw) * 4;
                LDSM_X4(kbh[2 * qd][0], kbh[2 * qd][1],
                        kbh[2 * qd + 1][0], kbh[2 * qd + 1][1], kh_b + bo);
                LDSM_X4(kbl[2 * qd][0], kbl[2 * qd][1],
                        kbl[2 * qd + 1][0], kbl[2 * qd + 1][1], kl_b + bo);
            }
#pragma unroll
            for (int ni = 0; ni < 8; ni++)
                MMA_F16(s[ni], qh[ks], kbh[ni]);
#pragma unroll
            for (int ni = 0; ni < 8; ni++)
                MMA_F16(s[ni], qh[ks], kbl[ni]);
#pragma unroll
            for (int ni = 0; ni < 8; ni++)
                MMA_F16(s[ni], ql[ks], kbh[ni]);
        }

        // ---- causal mask (only last two kt tiles can touch the diagonal) ----
        if (kt >= 2 * qt) {
            const int gr0 = qt * 128 + r0;
            const int gr1 = gr0 + 8;
#pragma unroll
            for (int ni = 0; ni < 8; ni++) {
                const int gc = kt * 64 + ni * 8 + tig * 2;
                if (gc > gr0)     s[ni][0] = -1.0e30f;
                if (gc + 1 > gr0) s[ni][1] = -1.0e30f;
                if (gc > gr1)     s[ni][2] = -1.0e30f;
                if (gc + 1 > gr1) s[ni][3] = -1.0e30f;
            }
        }

        // ---- online softmax (base 2) ----
        float mx0 = -1.0e30f, mx1 = -1.0e30f;
#pragma unroll
        for (int ni = 0; ni < 8; ni++) {
            mx0 = fmaxf(mx0, fmaxf(s[ni][0], s[ni][1]));
            mx1 = fmaxf(mx1, fmaxf(s[ni][2], s[ni][3]));
        }
        mx0 = fmaxf(mx0, __shfl_xor_sync(0xffffffffu, mx0, 1));
        mx0 = fmaxf(mx0, __shfl_xor_sync(0xffffffffu, mx0, 2));
        mx1 = fmaxf(mx1, __shfl_xor_sync(0xffffffffu, mx1, 1));
        mx1 = fmaxf(mx1, __shfl_xor_sync(0xffffffffu, mx1, 2));

        const float mn0 = fmaxf(m0, mx0);
        const float mn1 = fmaxf(m1, mx1);
        const float a0 = ex2f(m0 - mn0);
        const float a1 = ex2f(m1 - mn1);
        m0 = mn0; m1 = mn1;

        float sum0 = 0.0f, sum1 = 0.0f;
#pragma unroll
        for (int ni = 0; ni < 8; ni++) {
            s[ni][0] = ex2f(s[ni][0] - mn0);
            s[ni][1] = ex2f(s[ni][1] - mn0);
            s[ni][2] = ex2f(s[ni][2] - mn1);
            s[ni][3] = ex2f(s[ni][3] - mn1);
            sum0 += s[ni][0] + s[ni][1];
            sum1 += s[ni][2] + s[ni][3];
        }
        sum0 += __shfl_xor_sync(0xffffffffu, sum0, 1);
        sum0 += __shfl_xor_sync(0xffffffffu, sum0, 2);
        sum1 += __shfl_xor_sync(0xffffffffu, sum1, 1);
        sum1 += __shfl_xor_sync(0xffffffffu, sum1, 2);
        l0 = l0 * a0 + sum0;
        l1 = l1 * a1 + sum1;

#pragma unroll
        for (int ni = 0; ni < 8; ni++) {
            o[ni][0] *= a0; o[ni][1] *= a0;
            o[ni][2] *= a1; o[ni][3] *= a1;
        }

        // ---- O += P V : single fp16 P, single fp16 V ----
#pragma unroll
        for (int j = 0; j < 4; j++) {
            uint32_t pa[4];
            pa[0] = packh2(s[2 * j][0],     s[2 * j][1]);
            pa[1] = packh2(s[2 * j][2],     s[2 * j][3]);
            pa[2] = packh2(s[2 * j + 1][0], s[2 * j + 1][1]);
            pa[3] = packh2(s[2 * j + 1][2], s[2 * j + 1][3]);
            uint32_t vb[8][2];
#pragma unroll
            for (int qd = 0; qd < 4; qd++) {
                const uint32_t vo = ((qd * 16 + b_r) * KWP + j * 8 + b_kw) * 4;
                LDSM_X4(vb[2 * qd][0], vb[2 * qd][1],
                        vb[2 * qd + 1][0], vb[2 * qd + 1][1], vh_b + vo);
            }
#pragma unroll
            for (int ni = 0; ni < 8; ni++)
                MMA_F16(o[ni], pa, vb[ni]);
        }
    }

    // ---- epilogue: normalize, split (bf16 planes), store concat-head ----
    const float inv0 = 1.0f / l0;
    const float inv1 = 1.0f / l1;
    const int b = n >> 4;
    const int h = n & 15;
    const int rowg0 = b * S_LEN + qt * 128 + r0;
    const int rowg1 = rowg0 + 8;
#pragma unroll
    for (int ni = 0; ni < 8; ni++) {
        const int cw = h * 32 + ni * 4 + tig;
        uint32_t hw, lw;
        split2(o[ni][0] * inv0, o[ni][1] * inv0, hw, lw);
        g_AOh[(size_t)rowg0 * 512 + cw] = hw;
        g_AOl[(size_t)rowg0 * 512 + cw] = lw;
        split2(o[ni][2] * inv1, o[ni][3] * inv1, hw, lw);
        g_AOh[(size_t)rowg1 * 512 + cw] = hw;
        g_AOl[(size_t)rowg1 * 512 + cw] = lw;
    }
}

// ---------------------------------------------------------------------------
// kernel_launch: x, mask, Wq, bq, Wk, bk, Wv, bv, Wo, bo
// ---------------------------------------------------------------------------
extern "C" void kernel_launch(void* const* d_in, const int* in_sizes, int n_in,
                              void* d_out, int out_size)
{
    const float* x  = (const float*)d_in[0];
    const float* Wq = (const float*)d_in[2];
    const float* bq = (const float*)d_in[3];
    const float* Wk = (const float*)d_in[4];
    const float* bk = (const float*)d_in[5];
    const float* Wv = (const float*)d_in[6];
    const float* bv = (const float*)d_in[7];
    const float* Wo = (const float*)d_in[8];
    const float* bo = (const float*)d_in[9];
    float* out = (float*)d_out;

    uint32_t *xh, *xl, *Wqh, *Wql, *Wkh, *Wkl, *Wvh, *Wvl, *Woh, *Wol;
    uint32_t *Qh, *Ql, *Kh, *Kl, *Vth, *AOh, *AOl;
    cudaGetSymbolAddress((void**)&xh,  g_xh);  cudaGetSymbolAddress((void**)&xl,  g_xl);
    cudaGetSymbolAddress((void**)&Wqh, g_Wqh); cudaGetSymbolAddress((void**)&Wql, g_Wql);
    cudaGetSymbolAddress((void**)&Wkh, g_Wkh); cudaGetSymbolAddress((void**)&Wkl, g_Wkl);
    cudaGetSymbolAddress((void**)&Wvh, g_Wvh); cudaGetSymbolAddress((void**)&Wvl, g_Wvl);
    cudaGetSymbolAddress((void**)&Woh, g_Woh); cudaGetSymbolAddress((void**)&Wol, g_Wol);
    cudaGetSymbolAddress((void**)&Qh,  g_Qh);  cudaGetSymbolAddress((void**)&Ql,  g_Ql);
    cudaGetSymbolAddress((void**)&Kh,  g_Kh);  cudaGetSymbolAddress((void**)&Kl,  g_Kl);
    cudaGetSymbolAddress((void**)&Vth, g_Vth);
    cudaGetSymbolAddress((void**)&AOh, g_AOh); cudaGetSymbolAddress((void**)&AOl, g_AOl);

    split_bf16<<<(M_ROWS * DIM / 4 + 255) / 256, 256>>>(x, xh, xl, M_ROWS * DIM / 4);
    {
        W4Args a;
        a.in[0] = (const float4*)Wq; a.oh[0] = (uint2*)Wqh; a.ol[0] = (uint2*)Wql;
        a.in[1] = (const float4*)Wk; a.oh[1] = (uint2*)Wkh; a.ol[1] = (uint2*)Wkl;
        a.in[2] = (const float4*)Wv; a.oh[2] = (uint2*)Wvh; a.ol[2] = (uint2*)Wvl;
        a.in[3] = (const float4*)Wo; a.oh[3] = (uint2*)Woh; a.ol[3] = (uint2*)Wol;
        const int n4 = DIM * DIM / 4;
        split_w4<<<dim3((n4 + 255) / 256, 4), 256>>>(a, n4);
    }

    const int gsmem = 8 * GTILEW * (int)sizeof(uint32_t);  // 81920
    cudaFuncSetAttribute(gemm_qkv, cudaFuncAttributeMaxDynamicSharedMemorySize, gsmem);
    cudaFuncSetAttribute(gemm_o,   cudaFuncAttributeMaxDynamicSharedMemorySize, gsmem);

    // Fused QKV projection: grid.z selects Q/K/V
    {
        QKVArgs qa;
        qa.Bh[0] = Wqh; qa.Bl[0] = Wql; qa.bias[0] = bq; qa.outh[0] = Qh;  qa.outl[0] = Ql;
        qa.Bh[1] = Wkh; qa.Bl[1] = Wkl; qa.bias[1] = bk; qa.outh[1] = Kh;  qa.outl[1] = Kl;
        qa.Bh[2] = Wvh; qa.Bl[2] = Wvl; qa.bias[2] = bv; qa.outh[2] = Vth; qa.outl[2] = nullptr;
        gemm_qkv<<<dim3(DIM / 128, M_ROWS / 128, 3), 256, gsmem>>>(xh, xl, qa);
    }

    const int fsmem = FSMW * (int)sizeof(uint32_t);  // 55296
    cudaFuncSetAttribute(flash_f16, cudaFuncAttributeMaxDynamicSharedMemorySize, fsmem);
    flash_f16<<<dim3(S_LEN / 128, BATCH * NH), 256, fsmem>>>();

    gemm_o<<<dim3(DIM / 128, M_ROWS / 128), 256, gsmem>>>(AOh, AOl, Woh, Wol, bo, out);
}

// round 16
// speedup vs baseline: 1.0915x; 1.0036x over previous
#include <cuda_runtime.h>
#include <cuda_bf16.h>
#include <cuda_fp16.h>
#include <math.h>
#include <stdint.h>

#define S_LEN 2048
#define DIM   1024
#define NH    16
#define DHEAD 64
#define BATCH 2
#define M_ROWS (BATCH * S_LEN)   // 4096
#define NW     (M_ROWS * DIM / 2)
#define WW     (DIM * DIM / 2)

// GEMM planes: bf16x2-packed hi/lo (low half = even k)
__device__ uint32_t g_xh[NW],  g_xl[NW];
__device__ uint32_t g_Wqh[WW], g_Wql[WW];
__device__ uint32_t g_Wkh[WW], g_Wkl[WW];
__device__ uint32_t g_Wvh[WW], g_Wvl[WW];
__device__ uint32_t g_Woh[WW], g_Wol[WW];
// Flash planes: fp16x2-packed. Q pre-scaled by 0.125*log2(e).
__device__ uint32_t g_Qh[NW], g_Ql[NW];
__device__ uint32_t g_Kh[NW], g_Kl[NW];
__device__ uint32_t g_Vth[NW];            // V transposed [n][dh][s/2], single fp16
// AO planes: bf16 (feeds bf16 O-GEMM)
__device__ uint32_t g_AOh[NW], g_AOl[NW];

// ---------------------------------------------------------------------------
// Helpers
// ---------------------------------------------------------------------------
__device__ __forceinline__ uint32_t cvta_smem(const void* p) {
    return (uint32_t)__cvta_generic_to_shared(p);
}
__device__ __forceinline__ void cp_async16(uint32_t dst, const void* src) {
    asm volatile("cp.async.cg.shared.global [%0], [%1], 16;" :: "r"(dst), "l"(src));
}
__device__ __forceinline__ void cp_commit() {
    asm volatile("cp.async.commit_group;");
}
__device__ __forceinline__ uint32_t packbf(float e0, float e1) {
    uint32_t r;
    asm("cvt.rn.bf16x2.f32 %0, %1, %2;" : "=r"(r) : "f"(e1), "f"(e0));
    return r;
}
__device__ __forceinline__ void split2(float e0, float e1, uint32_t& h, uint32_t& l) {
    h = packbf(e0, e1);
    float h0 = __uint_as_float(h << 16);
    float h1 = __uint_as_float(h & 0xFFFF0000u);
    l = packbf(e0 - h0, e1 - h1);
}
__device__ __forceinline__ uint32_t packh2(float e0, float e1) {
    __half2 v = __floats2half2_rn(e0, e1);
    return *reinterpret_cast<uint32_t*>(&v);
}
__device__ __forceinline__ void split2h(float e0, float e1, uint32_t& h, uint32_t& l) {
    __half2 hv = __floats2half2_rn(e0, e1);
    h = *reinterpret_cast<uint32_t*>(&hv);
    float f0 = __half2float(__low2half(hv));
    float f1 = __half2float(__high2half(hv));
    __half2 lv = __floats2half2_rn(e0 - f0, e1 - f1);
    l = *reinterpret_cast<uint32_t*>(&lv);
}
__device__ __forceinline__ float ex2f(float x) {
    float r;
    asm("ex2.approx.f32 %0, %1;" : "=f"(r) : "f"(x));
    return r;
}

#define MMA_BF16(c, a, b)                                                     \
    asm("mma.sync.aligned.m16n8k16.row.col.f32.bf16.bf16.f32 "                \
        "{%0,%1,%2,%3}, {%4,%5,%6,%7}, {%8,%9}, {%0,%1,%2,%3};"               \
        : "+f"((c)[0]), "+f"((c)[1]), "+f"((c)[2]), "+f"((c)[3])              \
        : "r"((a)[0]), "r"((a)[1]), "r"((a)[2]), "r"((a)[3]),                 \
          "r"((b)[0]), "r"((b)[1]))

#define MMA_F16(c, a, b)                                                      \
    asm("mma.sync.aligned.m16n8k16.row.col.f32.f16.f16.f32 "                  \
        "{%0,%1,%2,%3}, {%4,%5,%6,%7}, {%8,%9}, {%0,%1,%2,%3};"               \
        : "+f"((c)[0]), "+f"((c)[1]), "+f"((c)[2]), "+f"((c)[3])              \
        : "r"((a)[0]), "r"((a)[1]), "r"((a)[2]), "r"((a)[3]),                 \
          "r"((b)[0]), "r"((b)[1]))

#define LDSM_X4(r0, r1, r2, r3, addr)                                         \
    asm volatile("ldmatrix.sync.aligned.m8n8.x4.shared.b16 {%0,%1,%2,%3}, [%4];" \
        : "=r"(r0), "=r"(r1), "=r"(r2), "=r"(r3) : "r"(addr))

// ---------------------------------------------------------------------------
// Prepass splits
// ---------------------------------------------------------------------------
__global__ void __launch_bounds__(256) split_bf16(
    const float* __restrict__ in, uint32_t* __restrict__ oh,
    uint32_t* __restrict__ ol, int n4)
{
    const int i = blockIdx.x * blockDim.x + threadIdx.x;
    if (i >= n4) return;
    float4 v = ((const float4*)in)[i];
    uint32_t h0, l0, h1, l1;
    split2(v.x, v.y, h0, l0);
    split2(v.z, v.w, h1, l1);
    ((uint2*)oh)[i] = make_uint2(h0, h1);
    ((uint2*)ol)[i] = make_uint2(l0, l1);
}

struct W4Args {
    const float4* in[4];
    uint2* oh[4];
    uint2* ol[4];
};

__global__ void __launch_bounds__(256) split_w4(W4Args a, int n4)
{
    const int z = blockIdx.y;
    const int i = blockIdx.x * blockDim.x + threadIdx.x;
    if (i >= n4) return;
    float4 v = a.in[z][i];
    uint32_t h0, l0, h1, l1;
    split2(v.x, v.y, h0, l0);
    split2(v.z, v.w, h1, l1);
    a.oh[z][i] = make_uint2(h0, h1);
    a.ol[z][i] = make_uint2(l0, l1);
}

// ---------------------------------------------------------------------------
// GEMM core: 256 threads, 8 warps (4m x 2n), warp tile 32x64, ldmatrix
// fragments, one barrier per K-chunk, 3xBF16.
// MODE 0: fp32 out; 1: Q fp16 planes; 2: K fp16 planes; 3: V transposed.
// ---------------------------------------------------------------------------
#define BKW 16
#define AWP 20
#define GTILEW (128 * AWP)
#define QSCALE (0.125f * 1.4426950408889634f)

struct QKVArgs {
    const uint32_t* Bh[3];
    const uint32_t* Bl[3];
    const float*    bias[3];
    uint32_t*       outh[3];
    uint32_t*       outl[3];
};

template <int MODE>
__device__ __forceinline__ void gemm_core(
    const uint32_t* __restrict__ Ahg, const uint32_t* __restrict__ Alg,
    const uint32_t* __restrict__ Bhg, const uint32_t* __restrict__ Blg,
    const float* __restrict__ bias,
    float* __restrict__ outf,
    uint32_t* __restrict__ outh, uint32_t* __restrict__ outl,
    uint32_t* gsm, int bm, int bn)
{
    uint32_t* Ahs = gsm;
    uint32_t* Als = Ahs + 2 * GTILEW;
    uint32_t* Bhs = Als + 2 * GTILEW;
    uint32_t* Bls = Bhs + 2 * GTILEW;

    const int tid  = threadIdx.x;
    const int lane = tid & 31;
    const int wid  = tid >> 5;
    const int wm = (wid >> 1) * 32;
    const int wn = (wid & 1) * 64;
    const int gid = lane >> 2;
    const int tig = lane & 3;

    const int a_r  = lane & 15;
    const int a_kw = ((lane >> 4) & 1) * 4;
    const int b_r  = (lane & 7) + ((lane >> 4) & 1) * 8;
    const int b_kw = ((lane >> 3) & 1) * 4;

    const int lrow = tid >> 2;
    const int lkw  = (tid & 3) * 4;
    const uint32_t* Ah0 = Ahg + (size_t)(bm + lrow) * 512 + lkw;
    const uint32_t* Al0 = Alg + (size_t)(bm + lrow) * 512 + lkw;
    const uint32_t* Bh0 = Bhg + (size_t)(bn + lrow) * 512 + lkw;
    const uint32_t* Bl0 = Blg + (size_t)(bn + lrow) * 512 + lkw;

    float acc[16][4];
#pragma unroll
    for (int i = 0; i < 16; i++)
#pragma unroll
        for (int j = 0; j < 4; j++) acc[i][j] = 0.0f;

    auto stage = [&](int buf, int ktw) {
        const int o  = buf * GTILEW + lrow * AWP + lkw;
        const int o2 = o + 64 * AWP;
        cp_async16(cvta_smem(Ahs + o),  Ah0 + ktw);
        cp_async16(cvta_smem(Ahs + o2), Ah0 + 64 * 512 + ktw);
        cp_async16(cvta_smem(Als + o),  Al0 + ktw);
        cp_async16(cvta_smem(Als + o2), Al0 + 64 * 512 + ktw);
        cp_async16(cvta_smem(Bhs + o),  Bh0 + ktw);
        cp_async16(cvta_smem(Bhs + o2), Bh0 + 64 * 512 + ktw);
        cp_async16(cvta_smem(Bls + o),  Bl0 + ktw);
        cp_async16(cvta_smem(Bls + o2), Bl0 + 64 * 512 + ktw);
        cp_commit();
    };

    stage(0, 0);

    int buf = 0;
    for (int ktw = 0; ktw < 512; ktw += BKW, buf ^= 1) {
        asm volatile("cp.async.wait_group 0;");
        __syncthreads();
        if (ktw + BKW < 512) stage(buf ^ 1, ktw + BKW);

        const uint32_t ah_b = cvta_smem(Ahs + buf * GTILEW);
        const uint32_t al_b = cvta_smem(Als + buf * GTILEW);
        const uint32_t bh_b = cvta_smem(Bhs + buf * GTILEW);
        const uint32_t bl_b = cvta_smem(Bls + buf * GTILEW);

#pragma unroll
        for (int ks = 0; ks < 2; ks++) {
            uint32_t ah[2][4], al[2][4];
#pragma unroll
            for (int mi = 0; mi < 2; mi++) {
                const uint32_t ao =
                    ((wm + mi * 16 + a_r) * AWP + ks * 8 + a_kw) * 4;
                LDSM_X4(ah[mi][0], ah[mi][1], ah[mi][2], ah[mi][3], ah_b + ao);
                LDSM_X4(al[mi][0], al[mi][1], al[mi][2], al[mi][3], al_b + ao);
            }
            uint32_t bh[8][2], bl[8][2];
#pragma unroll
            for (int qd = 0; qd < 4; qd++) {
                const uint32_t bo =
                    ((wn + qd * 16 + b_r) * AWP + ks * 8 + b_kw) * 4;
                LDSM_X4(bh[2 * qd][0], bh[2 * qd][1],
                        bh[2 * qd + 1][0], bh[2 * qd + 1][1], bh_b + bo);
                LDSM_X4(bl[2 * qd][0], bl[2 * qd][1],
                        bl[2 * qd + 1][0], bl[2 * qd + 1][1], bl_b + bo);
            }
#pragma unroll
            for (int mi = 0; mi < 2; mi++)
#pragma unroll
                for (int ni = 0; ni < 8; ni++)
                    MMA_BF16(acc[mi * 8 + ni], ah[mi], bh[ni]);
#pragma unroll
            for (int mi = 0; mi < 2; mi++)
#pragma unroll
                for (int ni = 0; ni < 8; ni++)
                    MMA_BF16(acc[mi * 8 + ni], ah[mi], bl[ni]);
#pragma unroll
            for (int mi = 0; mi < 2; mi++)
#pragma unroll
                for (int ni = 0; ni < 8; ni++)
                    MMA_BF16(acc[mi * 8 + ni], al[mi], bh[ni]);
        }
    }

#pragma unroll
    for (int mi = 0; mi < 2; mi++) {
#pragma unroll
        for (int ni = 0; ni < 8; ni++) {
            const int row = bm + wm + mi * 16 + gid;
            const int col = bn + wn + ni * 8 + tig * 2;
            const float b0 = bias[col];
            const float b1 = bias[col + 1];
            const float* c = acc[mi * 8 + ni];
#pragma unroll
            for (int half = 0; half < 2; half++) {
                const int m = row + half * 8;
                float v0 = c[half * 2 + 0] + b0;
                float v1 = c[half * 2 + 1] + b1;
                if (MODE == 0) {
                    float* dst = outf + (size_t)m * DIM + col;
                    dst[0] = v0;
                    dst[1] = v1;
                } else if (MODE == 1 || MODE == 2) {
                    if (MODE == 1) { v0 *= QSCALE; v1 *= QSCALE; }
                    const int b  = m / S_LEN;
                    const int s  = m % S_LEN;
                    const int h  = col / DHEAD;
                    const int dw = (col % DHEAD) >> 1;
                    const size_t idx = ((size_t)(b * NH + h) * S_LEN + s) * 32 + dw;
                    uint32_t hw, lw;
                    split2h(v0, v1, hw, lw);
                    outh[idx] = hw;
                    outl[idx] = lw;
                } else {  // MODE 3: V transposed, single fp16 plane [n][dh][s]
                    const int b  = m / S_LEN;
                    const int s  = m % S_LEN;
                    const int h  = col / DHEAD;
                    const int dh = col % DHEAD;
                    const int n  = b * NH + h;
                    __half* VH = (__half*)outh;
                    const size_t base = ((size_t)n * DHEAD + dh) * S_LEN + s;
                    VH[base]         = __float2half_rn(v0);
                    VH[base + S_LEN] = __float2half_rn(v1);
                }
            }
        }
    }
}

// Fused QKV: grid (8, 32, 3); z selects weight/bias/output + epilogue mode.
__global__ void __launch_bounds__(256, 2)
gemm_qkv(const uint32_t* __restrict__ Ahg, const uint32_t* __restrict__ Alg,
         QKVArgs args)
{
    extern __shared__ uint32_t gsm[];
    const int z  = blockIdx.z;
    const int bm = blockIdx.y * 128;
    const int bn = blockIdx.x * 128;
    if (z == 0) {
        gemm_core<1>(Ahg, Alg, args.Bh[0], args.Bl[0], args.bias[0],
                     nullptr, args.outh[0], args.outl[0], gsm, bm, bn);
    } else if (z == 1) {
        gemm_core<2>(Ahg, Alg, args.Bh[1], args.Bl[1], args.bias[1],
                     nullptr, args.outh[1], args.outl[1], gsm, bm, bn);
    } else {
        gemm_core<3>(Ahg, Alg, args.Bh[2], args.Bl[2], args.bias[2],
                     nullptr, args.outh[2], nullptr, gsm, bm, bn);
    }
}

// O projection: fp32 out.
__global__ void __launch_bounds__(256, 2)
gemm_o(const uint32_t* __restrict__ Ahg, const uint32_t* __restrict__ Alg,
       const uint32_t* __restrict__ Bhg, const uint32_t* __restrict__ Blg,
       const float* __restrict__ bias, float* __restrict__ outf)
{
    extern __shared__ uint32_t gsm[];
    gemm_core<0>(Ahg, Alg, Bhg, Blg, bias, outf, nullptr, nullptr,
                 gsm, blockIdx.y * 128, blockIdx.x * 128);
}

// ---------------------------------------------------------------------------
// Flash attention: QK = 3x fp16; PV = 1x fp16 + ONES-COLUMN MMA for row sums
// (l lives in accumulator o9 and is alpha-rescaled like O; no sum shfls).
// ldmatrix fragments, one barrier per kt, q-tile 128, base-2 softmax.
// ---------------------------------------------------------------------------
#define KWP 36
#define KVW (64 * KWP)
#define KVBUF (3 * KVW)
#define FSMW (2 * KVBUF)
#define H2_ONES 0x3C003C00u

__global__ void __launch_bounds__(256, 2) flash_f16()
{
    extern __shared__ uint32_t fsw[];

    const int qt   = (int)gridDim.x - 1 - (int)blockIdx.x;
    const int n    = blockIdx.y;
    const int tid  = threadIdx.x;
    const int lane = tid & 31;
    const int w    = tid >> 5;
    const int gid  = lane >> 2;
    const int tig  = lane & 3;

    const int r0 = w * 16 + gid;
    const int r1 = r0 + 8;

    const int b_r  = (lane & 7) + ((lane >> 4) & 1) * 8;
    const int b_kw = ((lane >> 3) & 1) * 4;

    const uint32_t* Qhg = g_Qh + ((size_t)n * S_LEN + qt * 128) * 32;
    const uint32_t* Qlg = g_Ql + ((size_t)n * S_LEN + qt * 128) * 32;
    uint32_t qh[4][4], ql[4][4];
#pragma unroll
    for (int ks = 0; ks < 4; ks++) {
        const int w0 = ks * 8 + tig;
        qh[ks][0] = Qhg[r0 * 32 + w0];
        qh[ks][1] = Qhg[r1 * 32 + w0];
        qh[ks][2] = Qhg[r0 * 32 + w0 + 4];
        qh[ks][3] = Qhg[r1 * 32 + w0 + 4];
        ql[ks][0] = Qlg[r0 * 32 + w0];
        ql[ks][1] = Qlg[r1 * 32 + w0];
        ql[ks][2] = Qlg[r0 * 32 + w0 + 4];
        ql[ks][3] = Qlg[r1 * 32 + w0 + 4];
    }

    float m0 = -1.0e30f, m1 = -1.0e30f;
    float o[8][4];
    float o9[4];   // ones-column accumulator: o9[0]=Σp row r0, o9[2]=row r1
#pragma unroll
    for (int i = 0; i < 8; i++)
#pragma unroll
        for (int j = 0; j < 4; j++) o[i][j] = 0.0f;
#pragma unroll
    for (int j = 0; j < 4; j++) o9[j] = 0.0f;

    const int srow = tid >> 2;
    const int soff = (tid & 3) * 8;

    const uint32_t* Khg = g_Kh  + (size_t)n * S_LEN * 32;
    const uint32_t* Klg = g_Kl  + (size_t)n * S_LEN * 32;
    const uint32_t* Vhg = g_Vth + (size_t)n * DHEAD * (S_LEN / 2);

    auto stage = [&](int buf, int kt) {
        const uint32_t* sKh = Khg + (size_t)(kt * 64 + srow) * 32 + soff;
        const uint32_t* sKl = Klg + (size_t)(kt * 64 + srow) * 32 + soff;
        const uint32_t* sVh = Vhg + (size_t)srow * (S_LEN / 2) + kt * 32 + soff;
        const uint32_t base = cvta_smem(fsw + buf * KVBUF + srow * KWP + soff);
        cp_async16(base,                    sKh);
        cp_async16(base + 16,               sKh + 4);
        cp_async16(base + KVW * 4,          sKl);
        cp_async16(base + KVW * 4 + 16,     sKl + 4);
        cp_async16(base + 2 * KVW * 4,      sVh);
        cp_async16(base + 2 * KVW * 4 + 16, sVh + 4);
        cp_commit();
    };

    const int ktmax = 2 * qt + 1;
    stage(0, 0);

    int buf = 0;
    for (int kt = 0; kt <= ktmax; kt++, buf ^= 1) {
        asm volatile("cp.async.wait_group 0;");
        __syncthreads();
        if (kt < ktmax) stage(buf ^ 1, kt + 1);

        const uint32_t kh_b = cvta_smem(fsw + buf * KVBUF);
        const uint32_t kl_b = kh_b + KVW * 4;
        const uint32_t vh_b = kh_b + 2 * KVW * 4;

        // ---- S = Q K^T (3x fp16, f32 acc; hh/hl/lh sweeps) ----
        float s[8][4];
#pragma unroll
        for (int i = 0; i < 8; i++)
#pragma unroll
            for (int j = 0; j < 4; j++) s[i][j] = 0.0f;

#pragma unroll
        for (int ks = 0; ks < 4; ks++) {
            uint32_t kbh[8][2], kbl[8][2];
#pragma unroll
            for (int qd = 0; qd < 4; qd++) {
                const uint32_t bo = ((qd * 16 + b_r) * KWP + ks * 8 + b_kw) * 4;
                LDSM_X4(kbh[2 * qd][0], kbh[2 * qd][1],
                        kbh[2 * qd + 1][0], kbh[2 * qd + 1][1], kh_b + bo);
                LDSM_X4(kbl[2 * qd][0], kbl[2 * qd][1],
                        kbl[2 * qd + 1][0], kbl[2 * qd + 1][1], kl_b + bo);
            }
#pragma unroll
            for (int ni = 0; ni < 8; ni++)
                MMA_F16(s[ni], qh[ks], kbh[ni]);
#pragma unroll
            for (int ni = 0; ni < 8; ni++)
                MMA_F16(s[ni], qh[ks], kbl[ni]);
#pragma unroll
            for (int ni = 0; ni < 8; ni++)
                MMA_F16(s[ni], ql[ks], kbh[ni]);
        }

        // ---- causal mask (only last two kt tiles can touch the diagonal) ----
        if (kt >= 2 * qt) {
            const int gr0 = qt * 128 + r0;
            const int gr1 = gr0 + 8;
#pragma unroll
            for (int ni = 0; ni < 8; ni++) {
                const int gc = kt * 64 + ni * 8 + tig * 2;
                if (gc > gr0)     s[ni][0] = -1.0e30f;
                if (gc + 1 > gr0) s[ni][1] = -1.0e30f;
                if (gc > gr1)     s[ni][2] = -1.0e30f;
                if (gc + 1 > gr1) s[ni][3] = -1.0e30f;
            }
        }

        // ---- online softmax (base 2); row sums come from the ones-MMA ----
        float mx0 = -1.0e30f, mx1 = -1.0e30f;
#pragma unroll
        for (int ni = 0; ni < 8; ni++) {
            mx0 = fmaxf(mx0, fmaxf(s[ni][0], s[ni][1]));
            mx1 = fmaxf(mx1, fmaxf(s[ni][2], s[ni][3]));
        }
        mx0 = fmaxf(mx0, __shfl_xor_sync(0xffffffffu, mx0, 1));
        mx0 = fmaxf(mx0, __shfl_xor_sync(0xffffffffu, mx0, 2));
        mx1 = fmaxf(mx1, __shfl_xor_sync(0xffffffffu, mx1, 1));
        mx1 = fmaxf(mx1, __shfl_xor_sync(0xffffffffu, mx1, 2));

        const float mn0 = fmaxf(m0, mx0);
        const float mn1 = fmaxf(m1, mx1);
        const float a0 = ex2f(m0 - mn0);
        const float a1 = ex2f(m1 - mn1);
        m0 = mn0; m1 = mn1;

#pragma unroll
        for (int ni = 0; ni < 8; ni++) {
            s[ni][0] = ex2f(s[ni][0] - mn0);
            s[ni][1] = ex2f(s[ni][1] - mn0);
            s[ni][2] = ex2f(s[ni][2] - mn1);
            s[ni][3] = ex2f(s[ni][3] - mn1);
        }

#pragma unroll
        for (int ni = 0; ni < 8; ni++) {
            o[ni][0] *= a0; o[ni][1] *= a0;
            o[ni][2] *= a1; o[ni][3] *= a1;
        }
        o9[0] *= a0; o9[1] *= a0;
        o9[2] *= a1; o9[3] *= a1;

        // ---- O += P V ; o9 += P x ones (row sums on the tensor pipe) ----
        const uint32_t vones[2] = { H2_ONES, H2_ONES };
#pragma unroll
        for (int j = 0; j < 4; j++) {
            uint32_t pa[4];
            pa[0] = packh2(s[2 * j][0],     s[2 * j][1]);
            pa[1] = packh2(s[2 * j][2],     s[2 * j][3]);
            pa[2] = packh2(s[2 * j + 1][0], s[2 * j + 1][1]);
            pa[3] = packh2(s[2 * j + 1][2], s[2 * j + 1][3]);
            uint32_t vb[8][2];
#pragma unroll
            for (int qd = 0; qd < 4; qd++) {
                const uint32_t vo = ((qd * 16 + b_r) * KWP + j * 8 + b_kw) * 4;
                LDSM_X4(vb[2 * qd][0], vb[2 * qd][1],
                        vb[2 * qd + 1][0], vb[2 * qd + 1][1], vh_b + vo);
            }
#pragma unroll
            for (int ni = 0; ni < 8; ni++)
                MMA_F16(o[ni], pa, vb[ni]);
            MMA_F16(o9, pa, vones);
        }
    }

    // ---- epilogue: normalize (l = o9), split, store concat-head ----
    const float inv0 = 1.0f / o9[0];
    const float inv1 = 1.0f / o9[2];
    const int b = n >> 4;
    const int h = n & 15;
    const int rowg0 = b * S_LEN + qt * 128 + r0;
    const int rowg1 = rowg0 + 8;
#pragma unroll
    for (int ni = 0; ni < 8; ni++) {
        const int cw = h * 32 + ni * 4 + tig;
        uint32_t hw, lw;
        split2(o[ni][0] * inv0, o[ni][1] * inv0, hw, lw);
        g_AOh[(size_t)rowg0 * 512 + cw] = hw;
        g_AOl[(size_t)rowg0 * 512 + cw] = lw;
        split2(o[ni][2] * inv1, o[ni][3] * inv1, hw, lw);
        g_AOh[(size_t)rowg1 * 512 + cw] = hw;
        g_AOl[(size_t)rowg1 * 512 + cw] = lw;
    }
}

// ---------------------------------------------------------------------------
// kernel_launch: x, mask, Wq, bq, Wk, bk, Wv, bv, Wo, bo
// ---------------------------------------------------------------------------
extern "C" void kernel_launch(void* const* d_in, const int* in_sizes, int n_in,
                              void* d_out, int out_size)
{
    const float* x  = (const float*)d_in[0];
    const float* Wq = (const float*)d_in[2];
    const float* bq = (const float*)d_in[3];
    const float* Wk = (const float*)d_in[4];
    const float* bk = (const float*)d_in[5];
    const float* Wv = (const float*)d_in[6];
    const float* bv = (const float*)d_in[7];
    const float* Wo = (const float*)d_in[8];
    const float* bo = (const float*)d_in[9];
    float* out = (float*)d_out;

    uint32_t *xh, *xl, *Wqh, *Wql, *Wkh, *Wkl, *Wvh, *Wvl, *Woh, *Wol;
    uint32_t *Qh, *Ql, *Kh, *Kl, *Vth, *AOh, *AOl;
    cudaGetSymbolAddress((void**)&xh,  g_xh);  cudaGetSymbolAddress((void**)&xl,  g_xl);
    cudaGetSymbolAddress((void**)&Wqh, g_Wqh); cudaGetSymbolAddress((void**)&Wql, g_Wql);
    cudaGetSymbolAddress((void**)&Wkh, g_Wkh); cudaGetSymbolAddress((void**)&Wkl, g_Wkl);
    cudaGetSymbolAddress((void**)&Wvh, g_Wvh); cudaGetSymbolAddress((void**)&Wvl, g_Wvl);
    cudaGetSymbolAddress((void**)&Woh, g_Woh); cudaGetSymbolAddress((void**)&Wol, g_Wol);
    cudaGetSymbolAddress((void**)&Qh,  g_Qh);  cudaGetSymbolAddress((void**)&Ql,  g_Ql);
    cudaGetSymbolAddress((void**)&Kh,  g_Kh);  cudaGetSymbolAddress((void**)&Kl,  g_Kl);
    cudaGetSymbolAddress((void**)&Vth, g_Vth);
    cudaGetSymbolAddress((void**)&AOh, g_AOh); cudaGetSymbolAddress((void**)&AOl, g_AOl);

    split_bf16<<<(M_ROWS * DIM / 4 + 255) / 256, 256>>>(x, xh, xl, M_ROWS * DIM / 4);
    {
        W4Args a;
        a.in[0] = (const float4*)Wq; a.oh[0] = (uint2*)Wqh; a.ol[0] = (uint2*)Wql;
        a.in[1] = (const float4*)Wk; a.oh[1] = (uint2*)Wkh; a.ol[1] = (uint2*)Wkl;
        a.in[2] = (const float4*)Wv; a.oh[2] = (uint2*)Wvh; a.ol[2] = (uint2*)Wvl;
        a.in[3] = (const float4*)Wo; a.oh[3] = (uint2*)Woh; a.ol[3] = (uint2*)Wol;
        const int n4 = DIM * DIM / 4;
        split_w4<<<dim3((n4 + 255) / 256, 4), 256>>>(a, n4);
    }

    const int gsmem = 8 * GTILEW * (int)sizeof(uint32_t);  // 81920
    cudaFuncSetAttribute(gemm_qkv, cudaFuncAttributeMaxDynamicSharedMemorySize, gsmem);
    cudaFuncSetAttribute(gemm_o,   cudaFuncAttributeMaxDynamicSharedMemorySize, gsmem);

    // Fused QKV projection: grid.z selects Q/K/V
    {
        QKVArgs qa;
        qa.Bh[0] = Wqh; qa.Bl[0] = Wql; qa.bias[0] = bq; qa.outh[0] = Qh;  qa.outl[0] = Ql;
        qa.Bh[1] = Wkh; qa.Bl[1] = Wkl; qa.bias[1] = bk; qa.outh[1] = Kh;  qa.outl[1] = Kl;
        qa.Bh[2] = Wvh; qa.Bl[2] = Wvl; qa.bias[2] = bv; qa.outh[2] = Vth; qa.outl[2] = nullptr;
        gemm_qkv<<<dim3(DIM / 128, M_ROWS / 128, 3), 256, gsmem>>>(xh, xl, qa);
    }

    const int fsmem = FSMW * (int)sizeof(uint32_t);  // 55296
    cudaFuncSetAttribute(flash_f16, cudaFuncAttributeMaxDynamicSharedMemorySize, fsmem);
    flash_f16<<<dim3(S_LEN / 128, BATCH * NH), 256, fsmem>>>();

    gemm_o<<<dim3(DIM / 128, M_ROWS / 128), 256, gsmem>>>(AOh, AOl, Woh, Wol, bo, out);
}